// round 12
// baseline (speedup 1.0000x reference)
#include <cuda_runtime.h>
#include <cuda_bf16.h>

// LengthRegulator: out[b,t,:] = x[b, searchsorted(cumsum(dur[b]), t, 'right'), :]
// (zeros for t >= total duration). Shapes fixed by the problem:
//   x: [16, 512, 512] f32, durations: [16, 512] i32, out: [16, 4096, 512] f32.
//
// Best-known structure: FPW=1 (one warp per output row, shortest uniform
// warps) + __stcs evict-first stores. This round: 256-thread blocks (8 rows
// per block) to halve the grid to 8192 blocks — same per-warp work, smaller
// launch/rasterization ramp than R11's 16384 blocks.

static constexpr int B  = 16;
static constexpr int S  = 512;
static constexpr int H  = 512;
static constexpr int T  = 4096;
static constexpr int H4 = H / 4;          // 128 float4 per row

// Scratch: per-frame source-token index (S means "invalid / zero frame").
__device__ int g_idx[B * T];

// One block per batch. Warp-shuffle inclusive scan, then scatter: token j
// writes its index over frames [cum[j-1], cum[j]); tail gets S.
__global__ void scan_idx_kernel(const int* __restrict__ durations) {
    __shared__ int warp_sums[16];
    __shared__ int s_total;
    const int b    = blockIdx.x;
    const int tid  = threadIdx.x;         // blockDim.x == S == 512
    const int lane = tid & 31;
    const int wid  = tid >> 5;            // 16 warps

    const int d = durations[b * S + tid];

    int v = d;
    #pragma unroll
    for (int off = 1; off < 32; off <<= 1) {
        int n = __shfl_up_sync(0xffffffffu, v, off);
        if (lane >= off) v += n;
    }
    if (lane == 31) warp_sums[wid] = v;
    __syncthreads();

    if (wid == 0 && lane < 16) {
        int w = warp_sums[lane];
        #pragma unroll
        for (int off = 1; off < 16; off <<= 1) {
            int n = __shfl_up_sync(0xffffu, w, off);
            if (lane >= off) w += n;
        }
        warp_sums[lane] = w;
        if (lane == 15) s_total = w;
    }
    __syncthreads();

    const int cum   = v + (wid > 0 ? warp_sums[wid - 1] : 0);  // inclusive
    const int start = cum - d;                                  // exclusive
    const int total = s_total;
    int* __restrict__ gi = g_idx + b * T;

    for (int t = start; t < cum; ++t) gi[t] = tid;
    for (int t = total + tid; t < T; t += S) gi[t] = S;
}

// One WARP per output row: 4 independent LDG.128 + 4 streaming STG.128 per
// lane, perfectly uniform, shortest possible warp lifetime.
__global__ void __launch_bounds__(256)
gather_kernel(const float4* __restrict__ x, float4* __restrict__ out) {
    const int row  = blockIdx.x * (blockDim.x >> 5) + (threadIdx.x >> 5);
    const int lane = threadIdx.x & 31;
    const int b    = row >> 12;           // / T

    const int idx = g_idx[row];           // warp-uniform (1 sector)
    float4* o = out + ((long long)row << 7);

    if (idx < S) {
        const float4* s = x + ((long long)((b << 9) + idx) << 7);
        float4 v0 = s[lane];
        float4 v1 = s[lane + 32];
        float4 v2 = s[lane + 64];
        float4 v3 = s[lane + 96];
        __stcs(&o[lane],      v0);
        __stcs(&o[lane + 32], v1);
        __stcs(&o[lane + 64], v2);
        __stcs(&o[lane + 96], v3);
    } else {
        const float4 z = make_float4(0.f, 0.f, 0.f, 0.f);
        __stcs(&o[lane],      z);
        __stcs(&o[lane + 32], z);
        __stcs(&o[lane + 64], z);
        __stcs(&o[lane + 96], z);
    }
}

extern "C" void kernel_launch(void* const* d_in, const int* in_sizes, int n_in,
                              void* d_out, int out_size) {
    const float* x   = (const float*)d_in[0];      // [B, S, H] f32
    const int*   dur = (const int*)d_in[1];        // [B, S]   i32
    float*       out = (float*)d_out;              // [B, T, H] f32
    (void)in_sizes; (void)n_in; (void)out_size;

    scan_idx_kernel<<<B, S>>>(dur);

    const int threads = 256;                       // 8 warps = 8 rows/block
    const int blocks  = (B * T) / (threads / 32);  // 8192
    gather_kernel<<<blocks, threads>>>((const float4*)x, (float4*)out);
}

// round 13
// speedup vs baseline: 1.0205x; 1.0205x over previous
#include <cuda_runtime.h>
#include <cuda_bf16.h>

// LengthRegulator: out[b,t,:] = x[b, searchsorted(cumsum(dur[b]), t, 'right'), :]
// (zeros for t >= total duration). Shapes fixed by the problem:
//   x: [16, 512, 512] f32, durations: [16, 512] i32, out: [16, 4096, 512] f32.
//
// R11 structure (best: FPW=1, 128-thread blocks, __stcs streaming stores)
// + PDL: the 16384-block gather grid dispatches while the scan kernel runs;
// gather blocks self-synchronize on griddepcontrol.wait before reading g_idx.

static constexpr int B  = 16;
static constexpr int S  = 512;
static constexpr int H  = 512;
static constexpr int T  = 4096;
static constexpr int H4 = H / 4;          // 128 float4 per row

// Scratch: per-frame source-token index (S means "invalid / zero frame").
__device__ int g_idx[B * T];

// One block per batch. Warp-shuffle inclusive scan, then scatter: token j
// writes its index over frames [cum[j-1], cum[j]); tail gets S. Signals
// dependents once this block's g_idx stores are complete.
__global__ void scan_idx_kernel(const int* __restrict__ durations) {
    __shared__ int warp_sums[16];
    __shared__ int s_total;
    const int b    = blockIdx.x;
    const int tid  = threadIdx.x;         // blockDim.x == S == 512
    const int lane = tid & 31;
    const int wid  = tid >> 5;            // 16 warps

    const int d = durations[b * S + tid];

    int v = d;
    #pragma unroll
    for (int off = 1; off < 32; off <<= 1) {
        int n = __shfl_up_sync(0xffffffffu, v, off);
        if (lane >= off) v += n;
    }
    if (lane == 31) warp_sums[wid] = v;
    __syncthreads();

    if (wid == 0 && lane < 16) {
        int w = warp_sums[lane];
        #pragma unroll
        for (int off = 1; off < 16; off <<= 1) {
            int n = __shfl_up_sync(0xffffu, w, off);
            if (lane >= off) w += n;
        }
        warp_sums[lane] = w;
        if (lane == 15) s_total = w;
    }
    __syncthreads();

    const int cum   = v + (wid > 0 ? warp_sums[wid - 1] : 0);  // inclusive
    const int start = cum - d;                                  // exclusive
    const int total = s_total;
    int* __restrict__ gi = g_idx + b * T;

    for (int t = start; t < cum; ++t) gi[t] = tid;
    for (int t = total + tid; t < T; t += S) gi[t] = S;

    __syncthreads();
    asm volatile("griddepcontrol.launch_dependents;" ::: "memory");
}

// One WARP per output row: 4 independent LDG.128 + 4 streaming STG.128 per
// lane, perfectly uniform, shortest possible warp lifetime.
__global__ void __launch_bounds__(128)
gather_kernel(const float4* __restrict__ x, float4* __restrict__ out) {
    const int row  = blockIdx.x * (blockDim.x >> 5) + (threadIdx.x >> 5);
    const int lane = threadIdx.x & 31;
    const int b    = row >> 12;           // / T

    // Block until the scan grid has published g_idx.
    asm volatile("griddepcontrol.wait;" ::: "memory");

    const int idx = g_idx[row];           // warp-uniform (1 sector)
    float4* o = out + ((long long)row << 7);

    if (idx < S) {
        const float4* s = x + ((long long)((b << 9) + idx) << 7);
        float4 v0 = s[lane];
        float4 v1 = s[lane + 32];
        float4 v2 = s[lane + 64];
        float4 v3 = s[lane + 96];
        __stcs(&o[lane],      v0);
        __stcs(&o[lane + 32], v1);
        __stcs(&o[lane + 64], v2);
        __stcs(&o[lane + 96], v3);
    } else {
        const float4 z = make_float4(0.f, 0.f, 0.f, 0.f);
        __stcs(&o[lane],      z);
        __stcs(&o[lane + 32], z);
        __stcs(&o[lane + 64], z);
        __stcs(&o[lane + 96], z);
    }
}

extern "C" void kernel_launch(void* const* d_in, const int* in_sizes, int n_in,
                              void* d_out, int out_size) {
    const float* x   = (const float*)d_in[0];      // [B, S, H] f32
    const int*   dur = (const int*)d_in[1];        // [B, S]   i32
    float*       out = (float*)d_out;              // [B, T, H] f32
    (void)in_sizes; (void)n_in; (void)out_size;

    scan_idx_kernel<<<B, S>>>(dur);

    const int threads = 128;                       // 4 warps = 4 rows/block
    const int blocks  = (B * T) / (threads / 32);  // 16384

    cudaLaunchConfig_t cfg = {};
    cfg.gridDim  = dim3(blocks, 1, 1);
    cfg.blockDim = dim3(threads, 1, 1);
    cfg.dynamicSmemBytes = 0;
    cfg.stream = 0;
    cudaLaunchAttribute attr[1];
    attr[0].id = cudaLaunchAttributeProgrammaticStreamSerialization;
    attr[0].val.programmaticStreamSerializationAllowed = 1;
    cfg.attrs = attr;
    cfg.numAttrs = 1;

    cudaLaunchKernelEx(&cfg, gather_kernel, (const float4*)x, (float4*)out);
}